// round 7
// baseline (speedup 1.0000x reference)
#include <cuda_runtime.h>
#include <math.h>

#define Bn 8
#define Cn 64
#define HW 65536
#define Sn 2048
#define OUTC 16
#define TCHUNK 256
#define NCHUNK 8                                  /* 2048 / TCHUNK */

#define F_SCALE     20.6096954f                   /* log2(e)/0.07 */
#define F_LN2       0.69314718056f

// f32x2 packed helpers ------------------------------------------------------
typedef unsigned long long ull;
__device__ __forceinline__ ull pack2(float lo, float hi) {
    ull r;
    asm("mov.b64 %0, {%1, %2};" : "=l"(r) : "r"(__float_as_uint(lo)), "r"(__float_as_uint(hi)));
    return r;
}
__device__ __forceinline__ void unpack2(ull v, float& lo, float& hi) {
    unsigned a, b;
    asm("mov.b64 {%0, %1}, %2;" : "=r"(a), "=r"(b) : "l"(v));
    lo = __uint_as_float(a); hi = __uint_as_float(b);
}
#define FMA2(d, a, b) asm("fma.rn.f32x2 %0, %1, %2, %3;" : "=l"(d) : "l"(a), "l"(b), "l"(d))
#define ADD2(d, a)    asm("add.rn.f32x2 %0, %1, %2;"     : "=l"(d) : "l"(a), "l"(d))
#define MUL2(d, a, b) asm("mul.rn.f32x2 %0, %1, %2;"     : "=l"(d) : "l"(a), "l"(b))
__device__ __forceinline__ float ex2f(float x) {
    float y; asm("ex2.approx.f32 %0, %1;" : "=f"(y) : "f"(x)); return y;
}
__device__ __forceinline__ float lg2f(float x) {
    float y; asm("lg2.approx.f32 %0, %1;" : "=f"(y) : "f"(x)); return y;
}

// Scratch
__device__ float g_diff[2 * Bn * Cn * Sn];          // 8 MB
__device__ float g_fq[Bn * Sn * OUTC];
__device__ float g_fk[Bn * Sn * OUTC];
__device__ float g_sums[NCHUNK * Bn * Sn];          // partial row sums, 512 KB

// ---------------------------------------------------------------------------
// Kernel A: gather + diff (+ zero the output scalar from block 0).
// ---------------------------------------------------------------------------
__global__ void gather_diff_kernel(const float* __restrict__ fq,
                                   const float* __restrict__ fk,
                                   const int*   __restrict__ c_ids,
                                   const int*   __restrict__ n_ids,
                                   float* __restrict__ out) {
    if (blockIdx.x == 0 && threadIdx.x == 0) out[0] = 0.0f;

    int gid = blockIdx.x;
    int map = gid >> 9;
    int bc  = gid & 511;
    int b   = bc >> 6;
    int c   = bc & 63;

    const float* feat = (map ? fk : fq) + ((size_t)b * Cn + c) * HW;
    float* dst = g_diff + ((size_t)(map * Bn + b) * Cn + c) * Sn;

    int j = threadIdx.x;
    float fc = __ldg(&feat[c_ids[j]]);

#pragma unroll
    for (int off = 0; off < 8; off++) {
        int s = off * 256 + j;
        dst[s] = fc - __ldg(&feat[n_ids[s]]);
    }
}

// ---------------------------------------------------------------------------
// Kernel B: MLP + L2-normalize (f32x2).  grid = 256, 128 threads.
// ---------------------------------------------------------------------------
#define XPAD 68
__global__ __launch_bounds__(128) void mlp_kernel(const float* __restrict__ W0,
                                                  const float* __restrict__ b0,
                                                  const float* __restrict__ W1,
                                                  const float* __restrict__ b1) {
    extern __shared__ float smem[];
    float* sx  = smem;                       // 128*68
    float* sW0 = sx + 128 * XPAD;            // 64*64  (transposed: [t][c])
    float* sW1 = sW0 + 64 * 64;              // 64*16
    float* sb0 = sW1 + 64 * 16;              // 64
    float* sb1 = sb0 + 64;                   // 16

    int mb = blockIdx.x >> 4;
    int s0 = (blockIdx.x & 15) * 128;
    int tid = threadIdx.x;

    const float* src = g_diff + (size_t)mb * Cn * Sn;

    for (int i = tid; i < 4096; i += 128) {
        int c = i >> 6, t = i & 63;
        sW0[t * 64 + c] = __ldg(&W0[i]);
    }
    for (int i = tid; i < 1024; i += 128) sW1[i] = __ldg(&W1[i]);
    if (tid < 64) sb0[tid] = __ldg(&b0[tid]);
    if (tid < 16) sb1[tid] = __ldg(&b1[tid]);

    for (int i = tid; i < 64 * 128; i += 128) {
        int c = i >> 7, s = i & 127;
        sx[s * XPAD + c] = src[(size_t)c * Sn + s0 + s];
    }
    __syncthreads();

    ull x2[32];
#pragma unroll
    for (int i = 0; i < 16; i++) {
        float4 v = *reinterpret_cast<float4*>(&sx[tid * XPAD + i * 4]);
        x2[2 * i + 0] = pack2(v.x, v.y);
        x2[2 * i + 1] = pack2(v.z, v.w);
    }

    ull o2[8];
#pragma unroll
    for (int i = 0; i < 8; i++) o2[i] = pack2(sb1[2 * i], sb1[2 * i + 1]);

#pragma unroll 4
    for (int t = 0; t < 64; t++) {
        const ull* w2 = reinterpret_cast<const ull*>(&sW0[t * 64]);
        ull a0 = 0, a1 = 0, a2 = 0, a3 = 0;
#pragma unroll
        for (int i = 0; i < 8; i++) {
            FMA2(a0, x2[i +  0], w2[i +  0]);
            FMA2(a1, x2[i +  8], w2[i +  8]);
            FMA2(a2, x2[i + 16], w2[i + 16]);
            FMA2(a3, x2[i + 24], w2[i + 24]);
        }
        ADD2(a0, a1); ADD2(a2, a3); ADD2(a0, a2);
        float lo, hi; unpack2(a0, lo, hi);
        float h = fmaxf(lo + hi + sb0[t], 0.0f);
        ull h2 = pack2(h, h);
        const ull* w1 = reinterpret_cast<const ull*>(&sW1[t * 16]);
#pragma unroll
        for (int i = 0; i < 8; i++) FMA2(o2[i], h2, w1[i]);
    }

    float o[16];
#pragma unroll
    for (int i = 0; i < 8; i++) unpack2(o2[i], o[2 * i], o[2 * i + 1]);

    float sq = 0.f;
#pragma unroll
    for (int i = 0; i < 16; i++) sq = fmaf(o[i], o[i], sq);
    float inv = 1.0f / (sqrtf(sq) + 1e-7f);

    float* dst = (mb < Bn ? g_fq + (size_t)mb * Sn * OUTC
                          : g_fk + (size_t)(mb - Bn) * Sn * OUTC)
                 + (size_t)(s0 + tid) * OUTC;
#pragma unroll
    for (int oo = 0; oo < 4; oo++) {
        float4 v = make_float4(o[oo * 4 + 0] * inv, o[oo * 4 + 1] * inv,
                               o[oo * 4 + 2] * inv, o[oo * 4 + 3] * inv);
        *reinterpret_cast<float4*>(&dst[oo * 4]) = v;
    }
}

// ---------------------------------------------------------------------------
// Kernel C: Gram partial sums (lane = row, k broadcast from smem).
//   Each lane owns one s-row; iterates its t-chunk; k_t is broadcast LDS.
//   partial[chunk][row] = sum_{t in chunk} exp2(q'.k_t - SCALE), q' = q*SCALE.
//   grid = 8 b x 8 rowgroups x 8 tchunks = 512 blocks, 256 threads, 16KB smem.
// ---------------------------------------------------------------------------
__global__ __launch_bounds__(256) void gram_kernel() {
    __shared__ float shk[TCHUNK * OUTC];     // 16 KB
    int blk = blockIdx.x;
    int b  = blk >> 6;
    int rg = (blk >> 3) & 7;
    int tc = blk & 7;

    // stage k chunk (coalesced)
    {
        const float4* src = reinterpret_cast<const float4*>(
            g_fk + ((size_t)b * Sn + tc * TCHUNK) * OUTC);
        float4* dst4 = reinterpret_cast<float4*>(shk);
        for (int i = threadIdx.x; i < TCHUNK * 4; i += 256)
            dst4[i] = src[i];
    }
    __syncthreads();

    int row = rg * 256 + threadIdx.x;        // row within batch, lane-contiguous

    // q' = q * SCALE, channel-pair packed (8 ull)
    ull q2[8];
    {
        const ull S2 = pack2(F_SCALE, F_SCALE);
        const float4* qr = reinterpret_cast<const float4*>(
            g_fq + ((size_t)b * Sn + row) * OUTC);
#pragma unroll
        for (int j = 0; j < 4; j++) {
            float4 v = __ldg(&qr[j]);
            ull p0 = pack2(v.x, v.y), p1 = pack2(v.z, v.w);
            MUL2(q2[2 * j + 0], p0, S2);
            MUL2(q2[2 * j + 1], p1, S2);
        }
    }

    const ull C2 = pack2(-F_SCALE, 0.0f);
    const ull* kk = reinterpret_cast<const ull*>(shk);
    float sum = 0.0f;

#pragma unroll 2
    for (int t = 0; t < TCHUNK; t += 2) {
        const ull* ka = kk + (size_t)t * 8;        // broadcast LDS.64
        const ull* kb = ka + 8;
        ull dA = C2, dB = C2;
#pragma unroll
        for (int c = 0; c < 8; c++) {
            FMA2(dA, q2[c], ka[c]);
            FMA2(dB, q2[c], kb[c]);
        }
        float lo, hi;
        unpack2(dA, lo, hi); sum = fmaf(ex2f(lo), ex2f(hi), sum);
        unpack2(dB, lo, hi); sum = fmaf(ex2f(lo), ex2f(hi), sum);
    }

    g_sums[(size_t)tc * (Bn * Sn) + (size_t)b * Sn + row] = sum;
}

// ---------------------------------------------------------------------------
// Kernel D: finalize.  One thread per row: total sum, diagonal dot, loss.
// grid = 64 blocks x 256 threads = 16384 rows.
// ---------------------------------------------------------------------------
__global__ __launch_bounds__(256) void finalize_kernel(float* __restrict__ out) {
    int r = blockIdx.x * 256 + threadIdx.x;      // global row 0..16383

    float sum = 0.f;
#pragma unroll
    for (int c = 0; c < NCHUNK; c++)
        sum += g_sums[(size_t)c * (Bn * Sn) + r];

    const float* q = g_fq + (size_t)r * OUTC;
    const float* k = g_fk + (size_t)r * OUTC;
    float d = 0.f;
#pragma unroll
    for (int c = 0; c < OUTC; c++) d = fmaf(q[c], k[c], d);

    // x_ss = SCALE*d - SCALE ; loss_row = ln2*(log2(sum) - x_ss)
    float loss = F_LN2 * (lg2f(sum) - F_SCALE * (d - 1.0f));

    // block reduce
#pragma unroll
    for (int o = 16; o > 0; o >>= 1)
        loss += __shfl_xor_sync(0xFFFFFFFFu, loss, o);
    __shared__ float red[8];
    int w = threadIdx.x >> 5, lane = threadIdx.x & 31;
    if (lane == 0) red[w] = loss;
    __syncthreads();
    if (threadIdx.x == 0) {
        float acc = 0.f;
#pragma unroll
        for (int i = 0; i < 8; i++) acc += red[i];
        atomicAdd(out, acc * (1.0f / (float)(Bn * Sn)));
    }
}

// ---------------------------------------------------------------------------
extern "C" void kernel_launch(void* const* d_in, const int* in_sizes, int n_in,
                              void* d_out, int out_size) {
    const float* f_q  = (const float*)d_in[0];
    const float* f_k  = (const float*)d_in[1];
    const float* W0   = (const float*)d_in[2];
    const float* b0   = (const float*)d_in[3];
    const float* W1   = (const float*)d_in[4];
    const float* b1   = (const float*)d_in[5];
    const int*   c_id = (const int*)d_in[6];
    const int*   n_id = (const int*)d_in[7];
    float* out = (float*)d_out;

    int mlp_smem = (128 * XPAD + 64 * 64 + 64 * 16 + 64 + 16) * (int)sizeof(float);
    cudaFuncSetAttribute(mlp_kernel,
                         cudaFuncAttributeMaxDynamicSharedMemorySize, mlp_smem);

    gather_diff_kernel<<<2 * Bn * Cn, 256>>>(f_q, f_k, c_id, n_id, out);
    mlp_kernel<<<16 * 16, 128, mlp_smem>>>(W0, b0, W1, b1);
    gram_kernel<<<512, 256>>>();
    finalize_kernel<<<64, 256>>>(out);
}

// round 8
// speedup vs baseline: 1.0070x; 1.0070x over previous
#include <cuda_runtime.h>
#include <math.h>

#define Bn 8
#define Cn 64
#define HW 65536
#define Sn 2048
#define OUTC 16
#define KTILE 1024                                /* k rows staged per pass */

#define F_SCALE     20.6096954f                   /* log2(e)/0.07 */
#define F_LN2       0.69314718056f

// f32x2 packed helpers ------------------------------------------------------
typedef unsigned long long ull;
__device__ __forceinline__ ull pack2(float lo, float hi) {
    ull r;
    asm("mov.b64 %0, {%1, %2};" : "=l"(r) : "r"(__float_as_uint(lo)), "r"(__float_as_uint(hi)));
    return r;
}
__device__ __forceinline__ void unpack2(ull v, float& lo, float& hi) {
    unsigned a, b;
    asm("mov.b64 {%0, %1}, %2;" : "=r"(a), "=r"(b) : "l"(v));
    lo = __uint_as_float(a); hi = __uint_as_float(b);
}
#define FMA2(d, a, b) asm("fma.rn.f32x2 %0, %1, %2, %3;" : "=l"(d) : "l"(a), "l"(b), "l"(d))
#define ADD2(d, a)    asm("add.rn.f32x2 %0, %1, %2;"     : "=l"(d) : "l"(a), "l"(d))
#define MUL2(d, a, b) asm("mul.rn.f32x2 %0, %1, %2;"     : "=l"(d) : "l"(a), "l"(b))
__device__ __forceinline__ float ex2f(float x) {
    float y; asm("ex2.approx.f32 %0, %1;" : "=f"(y) : "f"(x)); return y;
}
__device__ __forceinline__ float lg2f(float x) {
    float y; asm("lg2.approx.f32 %0, %1;" : "=f"(y) : "f"(x)); return y;
}

// Scratch
__device__ float g_diff[2 * Bn * Cn * Sn];      // 8 MB
__device__ float g_fq[Bn * Sn * OUTC];
__device__ float g_fk[Bn * Sn * OUTC];

// ---------------------------------------------------------------------------
// Kernel A: gather + diff (+ zero the output scalar from block 0).
// ---------------------------------------------------------------------------
__global__ void gather_diff_kernel(const float* __restrict__ fq,
                                   const float* __restrict__ fk,
                                   const int*   __restrict__ c_ids,
                                   const int*   __restrict__ n_ids,
                                   float* __restrict__ out) {
    if (blockIdx.x == 0 && threadIdx.x == 0) out[0] = 0.0f;

    int gid = blockIdx.x;
    int map = gid >> 9;
    int bc  = gid & 511;
    int b   = bc >> 6;
    int c   = bc & 63;

    const float* feat = (map ? fk : fq) + ((size_t)b * Cn + c) * HW;
    float* dst = g_diff + ((size_t)(map * Bn + b) * Cn + c) * Sn;

    int j = threadIdx.x;
    float fc = __ldg(&feat[c_ids[j]]);

#pragma unroll
    for (int off = 0; off < 8; off++) {
        int s = off * 256 + j;
        dst[s] = fc - __ldg(&feat[n_ids[s]]);
    }
}

// ---------------------------------------------------------------------------
// Kernel B: MLP + L2-normalize (f32x2).  grid = 256, 128 threads.
// ---------------------------------------------------------------------------
#define XPAD 68
__global__ __launch_bounds__(128) void mlp_kernel(const float* __restrict__ W0,
                                                  const float* __restrict__ b0,
                                                  const float* __restrict__ W1,
                                                  const float* __restrict__ b1) {
    extern __shared__ float smem[];
    float* sx  = smem;                       // 128*68
    float* sW0 = sx + 128 * XPAD;            // 64*64  (transposed: [t][c])
    float* sW1 = sW0 + 64 * 64;              // 64*16
    float* sb0 = sW1 + 64 * 16;              // 64
    float* sb1 = sb0 + 64;                   // 16

    int mb = blockIdx.x >> 4;
    int s0 = (blockIdx.x & 15) * 128;
    int tid = threadIdx.x;

    const float* src = g_diff + (size_t)mb * Cn * Sn;

    for (int i = tid; i < 4096; i += 128) {
        int c = i >> 6, t = i & 63;
        sW0[t * 64 + c] = __ldg(&W0[i]);
    }
    for (int i = tid; i < 1024; i += 128) sW1[i] = __ldg(&W1[i]);
    if (tid < 64) sb0[tid] = __ldg(&b0[tid]);
    if (tid < 16) sb1[tid] = __ldg(&b1[tid]);

    for (int i = tid; i < 64 * 128; i += 128) {
        int c = i >> 7, s = i & 127;
        sx[s * XPAD + c] = src[(size_t)c * Sn + s0 + s];
    }
    __syncthreads();

    ull x2[32];
#pragma unroll
    for (int i = 0; i < 16; i++) {
        float4 v = *reinterpret_cast<float4*>(&sx[tid * XPAD + i * 4]);
        x2[2 * i + 0] = pack2(v.x, v.y);
        x2[2 * i + 1] = pack2(v.z, v.w);
    }

    ull o2[8];
#pragma unroll
    for (int i = 0; i < 8; i++) o2[i] = pack2(sb1[2 * i], sb1[2 * i + 1]);

#pragma unroll 4
    for (int t = 0; t < 64; t++) {
        const ull* w2 = reinterpret_cast<const ull*>(&sW0[t * 64]);
        ull a0 = 0, a1 = 0, a2 = 0, a3 = 0;
#pragma unroll
        for (int i = 0; i < 8; i++) {
            FMA2(a0, x2[i +  0], w2[i +  0]);
            FMA2(a1, x2[i +  8], w2[i +  8]);
            FMA2(a2, x2[i + 16], w2[i + 16]);
            FMA2(a3, x2[i + 24], w2[i + 24]);
        }
        ADD2(a0, a1); ADD2(a2, a3); ADD2(a0, a2);
        float lo, hi; unpack2(a0, lo, hi);
        float h = fmaxf(lo + hi + sb0[t], 0.0f);
        ull h2 = pack2(h, h);
        const ull* w1 = reinterpret_cast<const ull*>(&sW1[t * 16]);
#pragma unroll
        for (int i = 0; i < 8; i++) FMA2(o2[i], h2, w1[i]);
    }

    float o[16];
#pragma unroll
    for (int i = 0; i < 8; i++) unpack2(o2[i], o[2 * i], o[2 * i + 1]);

    float sq = 0.f;
#pragma unroll
    for (int i = 0; i < 16; i++) sq = fmaf(o[i], o[i], sq);
    float inv = 1.0f / (sqrtf(sq) + 1e-7f);

    float* dst = (mb < Bn ? g_fq + (size_t)mb * Sn * OUTC
                          : g_fk + (size_t)(mb - Bn) * Sn * OUTC)
                 + (size_t)(s0 + tid) * OUTC;
#pragma unroll
    for (int oo = 0; oo < 4; oo++) {
        float4 v = make_float4(o[oo * 4 + 0] * inv, o[oo * 4 + 1] * inv,
                               o[oo * 4 + 2] * inv, o[oo * 4 + 3] * inv);
        *reinterpret_cast<float4*>(&dst[oo * 4]) = v;
    }
}

// ---------------------------------------------------------------------------
// Kernel C: PatchNCE loss (v6 — 2 rows/warp, 64KB 2-stage tile, 32 warps/SM).
//   x_st = q'.k_t - SCALE  (q' = q*SCALE);  loss_row = ln2*(log2(sum) - x_ss).
//   512 threads = 16 warps x 2 rows = 32 rows/block; grid = B*64 = 512.
//   k tile: 1024 rows (64 KB), 2 staging passes; sums accumulate across.
//   launch_bounds(512,2) caps regs at 63 -> 2 blocks/SM (regs+smem both fit).
// ---------------------------------------------------------------------------
__global__ __launch_bounds__(512, 2) void loss_kernel(float* __restrict__ out) {
    extern __shared__ float shk[];   // KTILE rows x 16 floats, swizzled chunks
    int b    = blockIdx.x >> 6;
    int tile = blockIdx.x & 63;

    const float* fkb = g_fk + (size_t)b * Sn * OUTC;
    const float* fqb = g_fq + (size_t)b * Sn * OUTC;

    int w    = threadIdx.x >> 5;      // 0..15
    int lane = threadIdx.x & 31;
    int s0   = tile * 32 + w * 2;

    // 2 q rows, channel-pair packed, prescaled by SCALE (8 ull per row)
    ull q2[2][8];
    {
        const ull S2 = pack2(F_SCALE, F_SCALE);
#pragma unroll
        for (int r = 0; r < 2; r++) {
            const float4* qr = reinterpret_cast<const float4*>(
                fqb + (size_t)(s0 + r) * OUTC);
#pragma unroll
            for (int j = 0; j < 4; j++) {
                float4 v = __ldg(&qr[j]);
                ull p0 = pack2(v.x, v.y), p1 = pack2(v.z, v.w);
                MUL2(q2[r][2 * j + 0], p0, S2);
                MUL2(q2[r][2 * j + 1], p1, S2);
            }
        }
    }

    const ull C2 = pack2(-F_SCALE, 0.0f);
    float sum0 = 0.f, sum1 = 0.f;

#pragma unroll
    for (int half = 0; half < 2; half++) {
        // stage 1024 k rows with 16B-chunk swizzle
        const float4* src = reinterpret_cast<const float4*>(
            fkb + (size_t)half * KTILE * OUTC);
        for (int i = threadIdx.x; i < KTILE * 4; i += 512) {
            int t = i >> 2, j = i & 3;
            float4 v = __ldg(&src[i]);
            int jj = j ^ ((t >> 1) & 3);
            *reinterpret_cast<float4*>(&shk[t * 16 + jj * 4]) = v;
        }
        __syncthreads();

        for (int t = lane; t < KTILE; t += 32) {
            const float* kb = &shk[t * 16];
            int sw = (t >> 1) & 3;
            ull k2[8];
#pragma unroll
            for (int j = 0; j < 4; j++) {
                float4 k = *reinterpret_cast<const float4*>(&kb[((j ^ sw) << 2)]);
                k2[2 * j + 0] = pack2(k.x, k.y);
                k2[2 * j + 1] = pack2(k.z, k.w);
            }
            ull d0 = C2, d1 = C2;
#pragma unroll
            for (int c = 0; c < 8; c++) {
                FMA2(d0, q2[0][c], k2[c]);
                FMA2(d1, q2[1][c], k2[c]);
            }
            float lo, hi;
            unpack2(d0, lo, hi); sum0 += ex2f(lo + hi);
            unpack2(d1, lo, hi); sum1 += ex2f(lo + hi);
        }
        __syncthreads();
    }

    // warp-reduce the 2 row sums
#pragma unroll
    for (int o = 16; o > 0; o >>= 1) {
        sum0 += __shfl_xor_sync(0xFFFFFFFFu, sum0, o);
        sum1 += __shfl_xor_sync(0xFFFFFFFFu, sum1, o);
    }

    // per-warp loss for 2 rows -> smem -> single atomic per block
    if (lane == 0) {
        float acc = 0.f;
#pragma unroll
        for (int r = 0; r < 2; r++) {
            int s = s0 + r;
            const float4* kr = reinterpret_cast<const float4*>(
                fkb + (size_t)s * OUTC);
            // x_ss = q'.k_s - SCALE   (q' regs hold q*SCALE)
            float d = -F_SCALE;
#pragma unroll
            for (int j = 0; j < 4; j++) {
                float4 kv = __ldg(&kr[j]);
                float qlo, qhi;
                unpack2(q2[r][2 * j + 0], qlo, qhi);
                d = fmaf(qlo, kv.x, d); d = fmaf(qhi, kv.y, d);
                unpack2(q2[r][2 * j + 1], qlo, qhi);
                d = fmaf(qlo, kv.z, d); d = fmaf(qhi, kv.w, d);
            }
            float sm = (r == 0) ? sum0 : sum1;
            acc += F_LN2 * (lg2f(sm) - d);
        }
        shk[w] = acc;
    }
    __syncthreads();
    if (threadIdx.x == 0) {
        float acc = 0.f;
#pragma unroll
        for (int i = 0; i < 16; i++) acc += shk[i];
        atomicAdd(out, acc * (1.0f / (float)(Bn * Sn)));
    }
}

// ---------------------------------------------------------------------------
extern "C" void kernel_launch(void* const* d_in, const int* in_sizes, int n_in,
                              void* d_out, int out_size) {
    const float* f_q  = (const float*)d_in[0];
    const float* f_k  = (const float*)d_in[1];
    const float* W0   = (const float*)d_in[2];
    const float* b0   = (const float*)d_in[3];
    const float* W1   = (const float*)d_in[4];
    const float* b1   = (const float*)d_in[5];
    const int*   c_id = (const int*)d_in[6];
    const int*   n_id = (const int*)d_in[7];
    float* out = (float*)d_out;

    int mlp_smem = (128 * XPAD + 64 * 64 + 64 * 16 + 64 + 16) * (int)sizeof(float);
    cudaFuncSetAttribute(mlp_kernel,
                         cudaFuncAttributeMaxDynamicSharedMemorySize, mlp_smem);
    int loss_smem = KTILE * OUTC * (int)sizeof(float);   // 64 KB
    cudaFuncSetAttribute(loss_kernel,
                         cudaFuncAttributeMaxDynamicSharedMemorySize, loss_smem);

    gather_diff_kernel<<<2 * Bn * Cn, 256>>>(f_q, f_k, c_id, n_id, out);
    mlp_kernel<<<16 * 16, 128, mlp_smem>>>(W0, b0, W1, b1);
    loss_kernel<<<Bn * 64, 512, loss_smem>>>(out);
}

// round 9
// speedup vs baseline: 1.0504x; 1.0432x over previous
#include <cuda_runtime.h>
#include <math.h>

#define Bn 8
#define Cn 64
#define HW 65536
#define Sn 2048
#define OUTC 16
#define TCH 256                                   /* t rows per gram block */

#define F_SCALE     20.6096954f                   /* log2(e)/0.07 */
#define F_LN2       0.69314718056f

// f32x2 packed helpers ------------------------------------------------------
typedef unsigned long long ull;
__device__ __forceinline__ ull pack2(float lo, float hi) {
    ull r;
    asm("mov.b64 %0, {%1, %2};" : "=l"(r) : "r"(__float_as_uint(lo)), "r"(__float_as_uint(hi)));
    return r;
}
__device__ __forceinline__ void unpack2(ull v, float& lo, float& hi) {
    unsigned a, b;
    asm("mov.b64 {%0, %1}, %2;" : "=r"(a), "=r"(b) : "l"(v));
    lo = __uint_as_float(a); hi = __uint_as_float(b);
}
#define FMA2(d, a, b) asm("fma.rn.f32x2 %0, %1, %2, %3;" : "=l"(d) : "l"(a), "l"(b), "l"(d))
#define ADD2(d, a)    asm("add.rn.f32x2 %0, %1, %2;"     : "=l"(d) : "l"(a), "l"(d))
#define MUL2(d, a, b) asm("mul.rn.f32x2 %0, %1, %2;"     : "=l"(d) : "l"(a), "l"(b))
__device__ __forceinline__ float ex2f(float x) {
    float y; asm("ex2.approx.f32 %0, %1;" : "=f"(y) : "f"(x)); return y;
}
__device__ __forceinline__ float lg2f(float x) {
    float y; asm("lg2.approx.f32 %0, %1;" : "=f"(y) : "f"(x)); return y;
}

// Scratch
__device__ float g_diff[2 * Bn * Cn * Sn];      // 8 MB
__device__ float g_fq[Bn * Sn * OUTC];
__device__ float g_fk[Bn * Sn * OUTC];
__device__ float g_sums[Bn * Sn];               // per-row exp-sum accumulators
__device__ int   g_cnt[64];                      // completion counters per (b,rg)

// ---------------------------------------------------------------------------
// Kernel A: gather + diff (+ zero out / g_sums / g_cnt).
// ---------------------------------------------------------------------------
__global__ void gather_diff_kernel(const float* __restrict__ fq,
                                   const float* __restrict__ fk,
                                   const int*   __restrict__ c_ids,
                                   const int*   __restrict__ n_ids,
                                   float* __restrict__ out) {
    if (blockIdx.x == 0 && threadIdx.x == 0) out[0] = 0.0f;
    if (blockIdx.x < 64) g_sums[blockIdx.x * 256 + threadIdx.x] = 0.0f;
    if (blockIdx.x == 64 && threadIdx.x < 64) g_cnt[threadIdx.x] = 0;

    int gid = blockIdx.x;
    int map = gid >> 9;
    int bc  = gid & 511;
    int b   = bc >> 6;
    int c   = bc & 63;

    const float* feat = (map ? fk : fq) + ((size_t)b * Cn + c) * HW;
    float* dst = g_diff + ((size_t)(map * Bn + b) * Cn + c) * Sn;

    int j = threadIdx.x;
    float fc = __ldg(&feat[c_ids[j]]);

#pragma unroll
    for (int off = 0; off < 8; off++) {
        int s = off * 256 + j;
        dst[s] = fc - __ldg(&feat[n_ids[s]]);
    }
}

// ---------------------------------------------------------------------------
// Kernel B: MLP + L2-normalize (f32x2).  grid = 256, 128 threads.
// ---------------------------------------------------------------------------
#define XPAD 68
__global__ __launch_bounds__(128) void mlp_kernel(const float* __restrict__ W0,
                                                  const float* __restrict__ b0,
                                                  const float* __restrict__ W1,
                                                  const float* __restrict__ b1) {
    extern __shared__ float smem[];
    float* sx  = smem;                       // 128*68
    float* sW0 = sx + 128 * XPAD;            // 64*64  (transposed: [t][c])
    float* sW1 = sW0 + 64 * 64;              // 64*16
    float* sb0 = sW1 + 64 * 16;              // 64
    float* sb1 = sb0 + 64;                   // 16

    int mb = blockIdx.x >> 4;
    int s0 = (blockIdx.x & 15) * 128;
    int tid = threadIdx.x;

    const float* src = g_diff + (size_t)mb * Cn * Sn;

    for (int i = tid; i < 4096; i += 128) {
        int c = i >> 6, t = i & 63;
        sW0[t * 64 + c] = __ldg(&W0[i]);
    }
    for (int i = tid; i < 1024; i += 128) sW1[i] = __ldg(&W1[i]);
    if (tid < 64) sb0[tid] = __ldg(&b0[tid]);
    if (tid < 16) sb1[tid] = __ldg(&b1[tid]);

    for (int i = tid; i < 64 * 128; i += 128) {
        int c = i >> 7, s = i & 127;
        sx[s * XPAD + c] = src[(size_t)c * Sn + s0 + s];
    }
    __syncthreads();

    ull x2[32];
#pragma unroll
    for (int i = 0; i < 16; i++) {
        float4 v = *reinterpret_cast<float4*>(&sx[tid * XPAD + i * 4]);
        x2[2 * i + 0] = pack2(v.x, v.y);
        x2[2 * i + 1] = pack2(v.z, v.w);
    }

    ull o2[8];
#pragma unroll
    for (int i = 0; i < 8; i++) o2[i] = pack2(sb1[2 * i], sb1[2 * i + 1]);

#pragma unroll 4
    for (int t = 0; t < 64; t++) {
        const ull* w2 = reinterpret_cast<const ull*>(&sW0[t * 64]);
        ull a0 = 0, a1 = 0, a2 = 0, a3 = 0;
#pragma unroll
        for (int i = 0; i < 8; i++) {
            FMA2(a0, x2[i +  0], w2[i +  0]);
            FMA2(a1, x2[i +  8], w2[i +  8]);
            FMA2(a2, x2[i + 16], w2[i + 16]);
            FMA2(a3, x2[i + 24], w2[i + 24]);
        }
        ADD2(a0, a1); ADD2(a2, a3); ADD2(a0, a2);
        float lo, hi; unpack2(a0, lo, hi);
        float h = fmaxf(lo + hi + sb0[t], 0.0f);
        ull h2 = pack2(h, h);
        const ull* w1 = reinterpret_cast<const ull*>(&sW1[t * 16]);
#pragma unroll
        for (int i = 0; i < 8; i++) FMA2(o2[i], h2, w1[i]);
    }

    float o[16];
#pragma unroll
    for (int i = 0; i < 8; i++) unpack2(o2[i], o[2 * i], o[2 * i + 1]);

    float sq = 0.f;
#pragma unroll
    for (int i = 0; i < 16; i++) sq = fmaf(o[i], o[i], sq);
    float inv = 1.0f / (sqrtf(sq) + 1e-7f);

    float* dst = (mb < Bn ? g_fq + (size_t)mb * Sn * OUTC
                          : g_fk + (size_t)(mb - Bn) * Sn * OUTC)
                 + (size_t)(s0 + tid) * OUTC;
#pragma unroll
    for (int oo = 0; oo < 4; oo++) {
        float4 v = make_float4(o[oo * 4 + 0] * inv, o[oo * 4 + 1] * inv,
                               o[oo * 4 + 2] * inv, o[oo * 4 + 3] * inv);
        *reinterpret_cast<float4*>(&dst[oo * 4]) = v;
    }
}

// ---------------------------------------------------------------------------
// Kernel C: Gram + fused finalize (lane = row, broadcast k).
//   Each thread owns one s-row; iterates a 256-row k chunk from smem via
//   UNIFORM LDS.128 (broadcast, 1 wavefront).  Partial exp-sums merge via
//   atomicAdd into g_sums; the 8th (last) block per (b,rg) computes
//   log + diagonal + loss for its 256 rows and atomically adds to out.
//   grid = 8b x 8rg x 8tc = 512 blocks, 256 threads, 16 KB smem.
// ---------------------------------------------------------------------------
__global__ __launch_bounds__(256, 4) void gram_kernel(float* __restrict__ out) {
    __shared__ float shk[TCH * OUTC];            // 16 KB
    __shared__ int   s_last;
    __shared__ float s_red[8];

    int blk = blockIdx.x;
    int b  = blk >> 6;
    int rg = (blk >> 3) & 7;
    int tc = blk & 7;
    int tid = threadIdx.x;

    // stage k chunk (coalesced, no swizzle needed — reads are broadcast)
    {
        const float4* src = reinterpret_cast<const float4*>(
            g_fk + ((size_t)b * Sn + tc * TCH) * OUTC);
        float4* dst4 = reinterpret_cast<float4*>(shk);
#pragma unroll
        for (int i = 0; i < 4; i++)
            dst4[tid + 256 * i] = __ldg(&src[tid + 256 * i]);
    }
    __syncthreads();

    int row  = rg * 256 + tid;                   // row within batch
    int grow = b * Sn + row;                     // global row

    // q' = q * SCALE, channel-pair packed (8 ull)
    ull q2[8];
    {
        const ull S2 = pack2(F_SCALE, F_SCALE);
        const float4* qr = reinterpret_cast<const float4*>(
            g_fq + (size_t)grow * OUTC);
#pragma unroll
        for (int j = 0; j < 4; j++) {
            float4 v = __ldg(&qr[j]);
            ull p0 = pack2(v.x, v.y), p1 = pack2(v.z, v.w);
            MUL2(q2[2 * j + 0], p0, S2);
            MUL2(q2[2 * j + 1], p1, S2);
        }
    }

    const ull C2 = pack2(-F_SCALE, 0.0f);
    const float4* sk4 = reinterpret_cast<const float4*>(shk);
    float s0 = 0.f, s1 = 0.f, s2 = 0.f, s3 = 0.f;

    // 4 independent t-chains for ILP; all LDS are warp-uniform (broadcast)
    for (int t = 0; t < TCH; t += 4) {
        ull dA = C2, dB = C2, dC = C2, dD = C2;
#pragma unroll
        for (int j = 0; j < 4; j++) {
            float4 ka = sk4[(t + 0) * 4 + j];
            float4 kb = sk4[(t + 1) * 4 + j];
            float4 kc = sk4[(t + 2) * 4 + j];
            float4 kd = sk4[(t + 3) * 4 + j];
            FMA2(dA, q2[2 * j + 0], pack2(ka.x, ka.y));
            FMA2(dA, q2[2 * j + 1], pack2(ka.z, ka.w));
            FMA2(dB, q2[2 * j + 0], pack2(kb.x, kb.y));
            FMA2(dB, q2[2 * j + 1], pack2(kb.z, kb.w));
            FMA2(dC, q2[2 * j + 0], pack2(kc.x, kc.y));
            FMA2(dC, q2[2 * j + 1], pack2(kc.z, kc.w));
            FMA2(dD, q2[2 * j + 0], pack2(kd.x, kd.y));
            FMA2(dD, q2[2 * j + 1], pack2(kd.z, kd.w));
        }
        float lo, hi;
        unpack2(dA, lo, hi); s0 += ex2f(lo + hi);
        unpack2(dB, lo, hi); s1 += ex2f(lo + hi);
        unpack2(dC, lo, hi); s2 += ex2f(lo + hi);
        unpack2(dD, lo, hi); s3 += ex2f(lo + hi);
    }

    atomicAdd(&g_sums[grow], (s0 + s1) + (s2 + s3));

    // completion check: last of the 8 tc-blocks for this (b,rg) finalizes
    __threadfence();
    __syncthreads();
    if (tid == 0) {
        int old = atomicAdd(&g_cnt[b * 8 + rg], 1);
        s_last = (old == 7);
    }
    __syncthreads();
    if (!s_last) return;

    // finalize: total sum (L2-coherent read), fp32 diagonal, loss
    float sum = __ldcg(&g_sums[grow]);
    const float4* qr = reinterpret_cast<const float4*>(g_fq + (size_t)grow * OUTC);
    const float4* kr = reinterpret_cast<const float4*>(g_fk + (size_t)grow * OUTC);
    float d = 0.f;
#pragma unroll
    for (int j = 0; j < 4; j++) {
        float4 qv = __ldg(&qr[j]);
        float4 kv = __ldg(&kr[j]);
        d = fmaf(qv.x, kv.x, d); d = fmaf(qv.y, kv.y, d);
        d = fmaf(qv.z, kv.z, d); d = fmaf(qv.w, kv.w, d);
    }
    float loss = F_LN2 * (lg2f(sum) - F_SCALE * (d - 1.0f));

#pragma unroll
    for (int o = 16; o > 0; o >>= 1)
        loss += __shfl_xor_sync(0xFFFFFFFFu, loss, o);
    int w = tid >> 5, lane = tid & 31;
    if (lane == 0) s_red[w] = loss;
    __syncthreads();
    if (tid == 0) {
        float acc = 0.f;
#pragma unroll
        for (int i = 0; i < 8; i++) acc += s_red[i];
        atomicAdd(out, acc * (1.0f / (float)(Bn * Sn)));
    }
}

// ---------------------------------------------------------------------------
extern "C" void kernel_launch(void* const* d_in, const int* in_sizes, int n_in,
                              void* d_out, int out_size) {
    const float* f_q  = (const float*)d_in[0];
    const float* f_k  = (const float*)d_in[1];
    const float* W0   = (const float*)d_in[2];
    const float* b0   = (const float*)d_in[3];
    const float* W1   = (const float*)d_in[4];
    const float* b1   = (const float*)d_in[5];
    const int*   c_id = (const int*)d_in[6];
    const int*   n_id = (const int*)d_in[7];
    float* out = (float*)d_out;

    int mlp_smem = (128 * XPAD + 64 * 64 + 64 * 16 + 64 + 16) * (int)sizeof(float);
    cudaFuncSetAttribute(mlp_kernel,
                         cudaFuncAttributeMaxDynamicSharedMemorySize, mlp_smem);

    gather_diff_kernel<<<2 * Bn * Cn, 256>>>(f_q, f_k, c_id, n_id, out);
    mlp_kernel<<<16 * 16, 128, mlp_smem>>>(W0, b0, W1, b1);
    gram_kernel<<<512, 256>>>(out);
}

// round 10
// speedup vs baseline: 1.0857x; 1.0336x over previous
#include <cuda_runtime.h>
#include <math.h>

#define Bn 8
#define Cn 64
#define HW 65536
#define Sn 2048
#define OUTC 16

#define F_SCALE     20.6096954f                   /* log2(e)/0.07 */
#define F_LN2       0.69314718056f

// f32x2 packed helpers ------------------------------------------------------
typedef unsigned long long ull;
__device__ __forceinline__ ull pack2(float lo, float hi) {
    ull r;
    asm("mov.b64 %0, {%1, %2};" : "=l"(r) : "r"(__float_as_uint(lo)), "r"(__float_as_uint(hi)));
    return r;
}
__device__ __forceinline__ void unpack2(ull v, float& lo, float& hi) {
    unsigned a, b;
    asm("mov.b64 {%0, %1}, %2;" : "=r"(a), "=r"(b) : "l"(v));
    lo = __uint_as_float(a); hi = __uint_as_float(b);
}
#define FMA2(d, a, b) asm("fma.rn.f32x2 %0, %1, %2, %3;" : "=l"(d) : "l"(a), "l"(b), "l"(d))
#define ADD2(d, a)    asm("add.rn.f32x2 %0, %1, %2;"     : "=l"(d) : "l"(a), "l"(d))
#define MUL2(d, a, b) asm("mul.rn.f32x2 %0, %1, %2;"     : "=l"(d) : "l"(a), "l"(b))
__device__ __forceinline__ float ex2f(float x) {
    float y; asm("ex2.approx.f32 %0, %1;" : "=f"(y) : "f"(x)); return y;
}
__device__ __forceinline__ float lg2f(float x) {
    float y; asm("lg2.approx.f32 %0, %1;" : "=f"(y) : "f"(x)); return y;
}

// Scratch
__device__ float g_diff[2 * Bn * Cn * Sn];      // 8 MB
__device__ float g_fq[Bn * Sn * OUTC];
__device__ float g_fk[Bn * Sn * OUTC];

// ---------------------------------------------------------------------------
// Kernel A: gather + diff (+ zero out).  grid = 1024 blocks, 256 threads.
// Streaming stores: g_diff is consumed once from L2 by the MLP.
// ---------------------------------------------------------------------------
__global__ void gather_diff_kernel(const float* __restrict__ fq,
                                   const float* __restrict__ fk,
                                   const int*   __restrict__ c_ids,
                                   const int*   __restrict__ n_ids,
                                   float* __restrict__ out) {
    if (blockIdx.x == 0 && threadIdx.x == 0) out[0] = 0.0f;

    int gid = blockIdx.x;
    int map = gid >> 9;
    int bc  = gid & 511;
    int b   = bc >> 6;
    int c   = bc & 63;

    const float* feat = (map ? fk : fq) + ((size_t)b * Cn + c) * HW;
    float* dst = g_diff + ((size_t)(map * Bn + b) * Cn + c) * Sn;

    int j = threadIdx.x;
    float fc = __ldg(&feat[c_ids[j]]);

#pragma unroll
    for (int off = 0; off < 8; off++) {
        int s = off * 256 + j;
        float v = fc - __ldg(&feat[n_ids[s]]);
        __stcg(&dst[s], v);
    }
}

// ---------------------------------------------------------------------------
// Kernel B: MLP + L2-normalize (f32x2).  grid = 128 blocks x 256 threads;
// each thread owns one row.  2 warps/SMSP hides the FMA chains.
// ---------------------------------------------------------------------------
#define XPAD 68
__global__ __launch_bounds__(256) void mlp_kernel(const float* __restrict__ W0,
                                                  const float* __restrict__ b0,
                                                  const float* __restrict__ W1,
                                                  const float* __restrict__ b1) {
    extern __shared__ float smem[];
    float* sx  = smem;                       // 256*68
    float* sW0 = sx + 256 * XPAD;            // 64*64  (transposed: [t][c])
    float* sW1 = sW0 + 64 * 64;              // 64*16
    float* sb0 = sW1 + 64 * 16;              // 64
    float* sb1 = sb0 + 64;                   // 16

    int mb = blockIdx.x >> 3;
    int s0 = (blockIdx.x & 7) * 256;
    int tid = threadIdx.x;

    const float* src = g_diff + (size_t)mb * Cn * Sn;

    for (int i = tid; i < 4096; i += 256) {
        int c = i >> 6, t = i & 63;
        sW0[t * 64 + c] = __ldg(&W0[i]);
    }
    for (int i = tid; i < 1024; i += 256) sW1[i] = __ldg(&W1[i]);
    if (tid < 64) sb0[tid] = __ldg(&b0[tid]);
    if (tid < 16) sb1[tid] = __ldg(&b1[tid]);

    // x tile transposed: coalesced reads of g_diff[c][s0+s]
    for (int i = tid; i < 64 * 256; i += 256) {
        int c = i >> 8, s = i & 255;
        sx[s * XPAD + c] = src[(size_t)c * Sn + s0 + s];
    }
    __syncthreads();

    ull x2[32];
#pragma unroll
    for (int i = 0; i < 16; i++) {
        float4 v = *reinterpret_cast<float4*>(&sx[tid * XPAD + i * 4]);
        x2[2 * i + 0] = pack2(v.x, v.y);
        x2[2 * i + 1] = pack2(v.z, v.w);
    }

    ull o2[8];
#pragma unroll
    for (int i = 0; i < 8; i++) o2[i] = pack2(sb1[2 * i], sb1[2 * i + 1]);

#pragma unroll 4
    for (int t = 0; t < 64; t++) {
        const ull* w2 = reinterpret_cast<const ull*>(&sW0[t * 64]);
        ull a0 = 0, a1 = 0, a2 = 0, a3 = 0;
#pragma unroll
        for (int i = 0; i < 8; i++) {
            FMA2(a0, x2[i +  0], w2[i +  0]);
            FMA2(a1, x2[i +  8], w2[i +  8]);
            FMA2(a2, x2[i + 16], w2[i + 16]);
            FMA2(a3, x2[i + 24], w2[i + 24]);
        }
        ADD2(a0, a1); ADD2(a2, a3); ADD2(a0, a2);
        float lo, hi; unpack2(a0, lo, hi);
        float h = fmaxf(lo + hi + sb0[t], 0.0f);
        ull h2 = pack2(h, h);
        const ull* w1 = reinterpret_cast<const ull*>(&sW1[t * 16]);
#pragma unroll
        for (int i = 0; i < 8; i++) FMA2(o2[i], h2, w1[i]);
    }

    float o[16];
#pragma unroll
    for (int i = 0; i < 8; i++) unpack2(o2[i], o[2 * i], o[2 * i + 1]);

    float sq = 0.f;
#pragma unroll
    for (int i = 0; i < 16; i++) sq = fmaf(o[i], o[i], sq);
    float inv = 1.0f / (sqrtf(sq) + 1e-7f);

    float* dst = (mb < Bn ? g_fq + (size_t)mb * Sn * OUTC
                          : g_fk + (size_t)(mb - Bn) * Sn * OUTC)
                 + (size_t)(s0 + tid) * OUTC;
#pragma unroll
    for (int oo = 0; oo < 4; oo++) {
        float4 v = make_float4(o[oo * 4 + 0] * inv, o[oo * 4 + 1] * inv,
                               o[oo * 4 + 2] * inv, o[oo * 4 + 3] * inv);
        *reinterpret_cast<float4*>(&dst[oo * 4]) = v;
    }
}

// ---------------------------------------------------------------------------
// Kernel C: PatchNCE loss (R6 configuration — best measured).
//   x_st = q'.k_t - SCALE  (q' = q*SCALE);  loss_row = ln2*(log2(sum) - x_ss).
//   512 threads = 16 warps x 4 rows = 64 rows/block; grid = B*32.
// ---------------------------------------------------------------------------
__global__ __launch_bounds__(512, 1) void loss_kernel(float* __restrict__ out) {
    extern __shared__ float shk[];   // 2048 rows x 16 floats, swizzled chunks
    int b    = blockIdx.x >> 5;
    int tile = blockIdx.x & 31;

    const float* fkb = g_fk + (size_t)b * Sn * OUTC;
    const float* fqb = g_fq + (size_t)b * Sn * OUTC;

    int w    = threadIdx.x >> 5;      // 0..15
    int lane = threadIdx.x & 31;
    int s0   = tile * 64 + w * 4;

    // 4 q rows, channel-pair packed, prescaled by SCALE — issued BEFORE the
    // staging loop so the global loads overlap the STS work.
    ull q2[4][8];
    {
        const ull S2 = pack2(F_SCALE, F_SCALE);
#pragma unroll
        for (int r = 0; r < 4; r++) {
            const float4* qr = reinterpret_cast<const float4*>(
                fqb + (size_t)(s0 + r) * OUTC);
#pragma unroll
            for (int j = 0; j < 4; j++) {
                float4 v = __ldg(&qr[j]);
                ull p0 = pack2(v.x, v.y), p1 = pack2(v.z, v.w);
                MUL2(q2[r][2 * j + 0], p0, S2);
                MUL2(q2[r][2 * j + 1], p1, S2);
            }
        }
    }

    // stage fk[b] with 16B-chunk swizzle (conflict-free STS and LDS)
    const float4* fkb4 = reinterpret_cast<const float4*>(fkb);
    for (int i = threadIdx.x; i < Sn * 4; i += blockDim.x) {
        int t = i >> 2, j = i & 3;
        float4 v = fkb4[i];
        int jj = j ^ ((t >> 1) & 3);
        *reinterpret_cast<float4*>(&shk[t * 16 + jj * 4]) = v;
    }
    __syncthreads();

    const ull C2 = pack2(-F_SCALE, 0.0f);
    float sum[4] = {0.f, 0.f, 0.f, 0.f};

    for (int t = lane; t < Sn; t += 32) {
        const float* kb = &shk[t * 16];
        int sw = (t >> 1) & 3;
        ull k2[8];
#pragma unroll
        for (int j = 0; j < 4; j++) {
            float4 k = *reinterpret_cast<const float4*>(&kb[((j ^ sw) << 2)]);
            k2[2 * j + 0] = pack2(k.x, k.y);
            k2[2 * j + 1] = pack2(k.z, k.w);
        }
        ull d0 = C2, d1 = C2, d2 = C2, d3 = C2;
#pragma unroll
        for (int c = 0; c < 8; c++) {
            FMA2(d0, q2[0][c], k2[c]);
            FMA2(d1, q2[1][c], k2[c]);
            FMA2(d2, q2[2][c], k2[c]);
            FMA2(d3, q2[3][c], k2[c]);
        }
        float lo, hi;
        unpack2(d0, lo, hi); sum[0] += ex2f(lo + hi);
        unpack2(d1, lo, hi); sum[1] += ex2f(lo + hi);
        unpack2(d2, lo, hi); sum[2] += ex2f(lo + hi);
        unpack2(d3, lo, hi); sum[3] += ex2f(lo + hi);
    }

#pragma unroll
    for (int r = 0; r < 4; r++) {
#pragma unroll
        for (int o = 16; o > 0; o >>= 1)
            sum[r] += __shfl_xor_sync(0xFFFFFFFFu, sum[r], o);
    }

    if (lane == 0) {
        float acc = 0.f;
#pragma unroll
        for (int r = 0; r < 4; r++) {
            int s = s0 + r;
            int sw = (s >> 1) & 3;
            const float* ks = &shk[s * 16];
            float d = -F_SCALE;          // x_ss = q'.k_s - SCALE
#pragma unroll
            for (int c = 0; c < 16; c++) {
                int j = c >> 2;
                float kv = ks[((j ^ sw) << 2) + (c & 3)];
                float qlo, qhi;
                unpack2(q2[r][c >> 1], qlo, qhi);
                d = fmaf((c & 1) ? qhi : qlo, kv, d);
            }
            acc += F_LN2 * (lg2f(sum[r]) - d);
        }
        atomicAdd(out, acc * (1.0f / (float)(Bn * Sn)));
    }
}

// ---------------------------------------------------------------------------
extern "C" void kernel_launch(void* const* d_in, const int* in_sizes, int n_in,
                              void* d_out, int out_size) {
    const float* f_q  = (const float*)d_in[0];
    const float* f_k  = (const float*)d_in[1];
    const float* W0   = (const float*)d_in[2];
    const float* b0   = (const float*)d_in[3];
    const float* W1   = (const float*)d_in[4];
    const float* b1   = (const float*)d_in[5];
    const int*   c_id = (const int*)d_in[6];
    const int*   n_id = (const int*)d_in[7];
    float* out = (float*)d_out;

    int mlp_smem = (256 * XPAD + 64 * 64 + 64 * 16 + 64 + 16) * (int)sizeof(float);
    cudaFuncSetAttribute(mlp_kernel,
                         cudaFuncAttributeMaxDynamicSharedMemorySize, mlp_smem);
    cudaFuncSetAttribute(loss_kernel,
                         cudaFuncAttributeMaxDynamicSharedMemorySize,
                         Sn * OUTC * (int)sizeof(float));

    gather_diff_kernel<<<2 * Bn * Cn, 256>>>(f_q, f_k, c_id, n_id, out);
    mlp_kernel<<<16 * 8, 256, mlp_smem>>>(W0, b0, W1, b1);
    loss_kernel<<<Bn * 32, 512, Sn * OUTC * (int)sizeof(float)>>>(out);
}

// round 12
// speedup vs baseline: 1.4748x; 1.3583x over previous
#include <cuda_runtime.h>
#include <cuda_bf16.h>
#include <math.h>
#include <cstdint>

#define Bn 8
#define Cn 64
#define HW 65536
#define Sn 2048
#define OUTC 16

#define F_SCALE     20.6096954f                   /* log2(e)/0.07 */
#define F_LN2       0.69314718056f

typedef unsigned long long ull;
__device__ __forceinline__ ull pack2(float lo, float hi) {
    ull r;
    asm("mov.b64 %0, {%1, %2};" : "=l"(r) : "r"(__float_as_uint(lo)), "r"(__float_as_uint(hi)));
    return r;
}
__device__ __forceinline__ void unpack2(ull v, float& lo, float& hi) {
    unsigned a, b;
    asm("mov.b64 {%0, %1}, %2;" : "=r"(a), "=r"(b) : "l"(v));
    lo = __uint_as_float(a); hi = __uint_as_float(b);
}
#define FMA2(d, a, b) asm("fma.rn.f32x2 %0, %1, %2, %3;" : "=l"(d) : "l"(a), "l"(b), "l"(d))
#define ADD2(d, a)    asm("add.rn.f32x2 %0, %1, %2;"     : "=l"(d) : "l"(a), "l"(d))
__device__ __forceinline__ float ex2f(float x) {
    float y; asm("ex2.approx.f32 %0, %1;" : "=f"(y) : "f"(x)); return y;
}
__device__ __forceinline__ float lg2f(float x) {
    float y; asm("lg2.approx.f32 %0, %1;" : "=f"(y) : "f"(x)); return y;
}
#define PACKBF(d, lo, hi) \
    asm("cvt.rn.bf16x2.f32 %0, %1, %2;" : "=r"(d) : "f"(hi), "f"(lo))

// m16n8k16 bf16 MMA, C = 0 (K=16 == OUTC: one MMA = finished dot tile)
__device__ __forceinline__ void mma16816(float& d0, float& d1, float& d2, float& d3,
                                         uint32_t a0, uint32_t a1, uint32_t a2, uint32_t a3,
                                         uint32_t b0, uint32_t b1) {
    asm("mma.sync.aligned.m16n8k16.row.col.f32.bf16.bf16.f32 "
        "{%0,%1,%2,%3}, {%4,%5,%6,%7}, {%8,%9}, {%10,%11,%12,%13};"
        : "=f"(d0), "=f"(d1), "=f"(d2), "=f"(d3)
        : "r"(a0), "r"(a1), "r"(a2), "r"(a3), "r"(b0), "r"(b1),
          "f"(0.0f), "f"(0.0f), "f"(0.0f), "f"(0.0f));
}

// Scratch
__device__ float g_diff[2 * Bn * Cn * Sn];      // 8 MB
__device__ float g_fq[Bn * Sn * OUTC];
__device__ float g_fk[Bn * Sn * OUTC];
__device__ __align__(16) __nv_bfloat16 g_fqh[Bn * Sn * OUTC];
__device__ __align__(16) __nv_bfloat16 g_fkh[Bn * Sn * OUTC];

// ---------------------------------------------------------------------------
// Kernel A: gather + diff (+ zero out).
// ---------------------------------------------------------------------------
__global__ void gather_diff_kernel(const float* __restrict__ fq,
                                   const float* __restrict__ fk,
                                   const int*   __restrict__ c_ids,
                                   const int*   __restrict__ n_ids,
                                   float* __restrict__ out) {
    if (blockIdx.x == 0 && threadIdx.x == 0) out[0] = 0.0f;

    int gid = blockIdx.x;
    int map = gid >> 9;
    int bc  = gid & 511;
    int b   = bc >> 6;
    int c   = bc & 63;

    const float* feat = (map ? fk : fq) + ((size_t)b * Cn + c) * HW;
    float* dst = g_diff + ((size_t)(map * Bn + b) * Cn + c) * Sn;

    int j = threadIdx.x;
    float fc = __ldg(&feat[c_ids[j]]);

#pragma unroll
    for (int off = 0; off < 8; off++) {
        int s = off * 256 + j;
        float v = fc - __ldg(&feat[n_ids[s]]);
        __stcg(&dst[s], v);
    }
}

// ---------------------------------------------------------------------------
// Kernel B: MLP + L2-normalize; emits fp32 AND bf16 embeddings.
// ---------------------------------------------------------------------------
#define XPAD 68
__global__ __launch_bounds__(256) void mlp_kernel(const float* __restrict__ W0,
                                                  const float* __restrict__ b0,
                                                  const float* __restrict__ W1,
                                                  const float* __restrict__ b1) {
    extern __shared__ float smem[];
    float* sx  = smem;                       // 256*68
    float* sW0 = sx + 256 * XPAD;            // 64*64 (transposed)
    float* sW1 = sW0 + 64 * 64;              // 64*16
    float* sb0 = sW1 + 64 * 16;              // 64
    float* sb1 = sb0 + 64;                   // 16

    int mb = blockIdx.x >> 3;
    int s0 = (blockIdx.x & 7) * 256;
    int tid = threadIdx.x;

    const float* src = g_diff + (size_t)mb * Cn * Sn;

    for (int i = tid; i < 4096; i += 256) {
        int c = i >> 6, t = i & 63;
        sW0[t * 64 + c] = __ldg(&W0[i]);
    }
    for (int i = tid; i < 1024; i += 256) sW1[i] = __ldg(&W1[i]);
    if (tid < 64) sb0[tid] = __ldg(&b0[tid]);
    if (tid < 16) sb1[tid] = __ldg(&b1[tid]);

    for (int i = tid; i < 64 * 256; i += 256) {
        int c = i >> 8, s = i & 255;
        sx[s * XPAD + c] = src[(size_t)c * Sn + s0 + s];
    }
    __syncthreads();

    ull x2[32];
#pragma unroll
    for (int i = 0; i < 16; i++) {
        float4 v = *reinterpret_cast<float4*>(&sx[tid * XPAD + i * 4]);
        x2[2 * i + 0] = pack2(v.x, v.y);
        x2[2 * i + 1] = pack2(v.z, v.w);
    }

    ull o2[8];
#pragma unroll
    for (int i = 0; i < 8; i++) o2[i] = pack2(sb1[2 * i], sb1[2 * i + 1]);

#pragma unroll 4
    for (int t = 0; t < 64; t++) {
        const ull* w2 = reinterpret_cast<const ull*>(&sW0[t * 64]);
        ull a0 = 0, a1 = 0, a2 = 0, a3 = 0;
#pragma unroll
        for (int i = 0; i < 8; i++) {
            FMA2(a0, x2[i +  0], w2[i +  0]);
            FMA2(a1, x2[i +  8], w2[i +  8]);
            FMA2(a2, x2[i + 16], w2[i + 16]);
            FMA2(a3, x2[i + 24], w2[i + 24]);
        }
        ADD2(a0, a1); ADD2(a2, a3); ADD2(a0, a2);
        float lo, hi; unpack2(a0, lo, hi);
        float h = fmaxf(lo + hi + sb0[t], 0.0f);
        ull h2 = pack2(h, h);
        const ull* w1 = reinterpret_cast<const ull*>(&sW1[t * 16]);
#pragma unroll
        for (int i = 0; i < 8; i++) FMA2(o2[i], h2, w1[i]);
    }

    float o[16];
#pragma unroll
    for (int i = 0; i < 8; i++) unpack2(o2[i], o[2 * i], o[2 * i + 1]);

    float sq = 0.f;
#pragma unroll
    for (int i = 0; i < 16; i++) sq = fmaf(o[i], o[i], sq);
    float inv = 1.0f / (sqrtf(sq) + 1e-7f);
#pragma unroll
    for (int i = 0; i < 16; i++) o[i] *= inv;

    size_t row = (mb < Bn) ? ((size_t)mb * Sn + s0 + tid)
                           : ((size_t)(mb - Bn) * Sn + s0 + tid);
    float* dst = (mb < Bn ? g_fq : g_fk) + row * OUTC;
#pragma unroll
    for (int oo = 0; oo < 4; oo++)
        *reinterpret_cast<float4*>(&dst[oo * 4]) =
            make_float4(o[oo * 4 + 0], o[oo * 4 + 1], o[oo * 4 + 2], o[oo * 4 + 3]);

    uint32_t hb[8];
#pragma unroll
    for (int i = 0; i < 8; i++) PACKBF(hb[i], o[2 * i], o[2 * i + 1]);
    uint32_t* dsth = reinterpret_cast<uint32_t*>(
        (mb < Bn ? g_fqh : g_fkh) + row * OUTC);
#pragma unroll
    for (int i = 0; i < 2; i++)
        reinterpret_cast<uint4*>(dsth)[i] =
            make_uint4(hb[4 * i + 0], hb[4 * i + 1], hb[4 * i + 2], hb[4 * i + 3]);
}

// ---------------------------------------------------------------------------
// Kernel C: HMMA Gram + fused softmax-sum + loss.
//   grid = 8b x 16 rowblocks = 128 CTAs, 256 threads (8 warps x 16 rows).
//   A fragments in regs (one m16k16 tile per warp, loaded once).
//   fk[b] (2048x16 bf16) staged in smem as B0/B1 halves (16B row stride ->
//   B-fragment LDS is conflict-free: word index = n*4+t covers all 32 banks).
//   Mainloop: 256 m16n8k16 MMAs per warp, C=0; accumulators go straight
//   through ex2 into per-row register sums.  Diagonal recomputed in fp32.
// ---------------------------------------------------------------------------
__global__ __launch_bounds__(256) void gram_kernel(float* __restrict__ out) {
    extern __shared__ uint32_t sk[];      // B0[2048*4] | B1[2048*4]  (64 KB)
    __shared__ float s_wred[8];

    int tid  = threadIdx.x;
    int w    = tid >> 5;
    int lane = tid & 31;
    int g    = lane >> 2;                 // groupID 0..7
    int t    = lane & 3;                  // threadID-in-group
    int b    = blockIdx.x >> 4;
    int rb   = blockIdx.x & 15;

    uint32_t* B0 = sk;
    uint32_t* B1 = sk + Sn * 4;

    // stage fk[b]: u32 idx -> row n = idx>>3, k-pair j = idx&7
    const uint32_t* ksrc = reinterpret_cast<const uint32_t*>(g_fkh) +
                           (size_t)b * Sn * 8;
    for (int idx = tid; idx < Sn * 8; idx += 256) {
        int n = idx >> 3, j = idx & 7;
        uint32_t v = __ldg(&ksrc[idx]);
        if (j < 4) B0[n * 4 + j] = v;
        else       B1[n * 4 + (j - 4)] = v;
    }

    // A fragment: warp covers q rows r0..r0+15
    int r0 = rb * 128 + w * 16 + g;
    const uint32_t* qu = reinterpret_cast<const uint32_t*>(g_fqh) +
                         (size_t)b * Sn * 8;
    uint32_t a0 = __ldg(&qu[(size_t)r0 * 8 + t]);
    uint32_t a1 = __ldg(&qu[(size_t)(r0 + 8) * 8 + t]);
    uint32_t a2 = __ldg(&qu[(size_t)r0 * 8 + t + 4]);
    uint32_t a3 = __ldg(&qu[(size_t)(r0 + 8) * 8 + t + 4]);

    __syncthreads();

    float s0 = 0.f, s1 = 0.f;    // row sums for rows r0 and r0+8 (cols 2t,2t+1 mod 8)

    for (int j = 0; j < Sn / 8; j += 2) {
        int nA = (j + 0) * 8 + g;
        int nB = (j + 1) * 8 + g;
        uint32_t bA0 = B0[nA * 4 + t], bA1 = B1[nA * 4 + t];
        uint32_t bB0 = B0[nB * 4 + t], bB1 = B1[nB * 4 + t];

        float dA0, dA1, dA2, dA3, dB0, dB1, dB2, dB3;
        mma16816(dA0, dA1, dA2, dA3, a0, a1, a2, a3, bA0, bA1);
        mma16816(dB0, dB1, dB2, dB3, a0, a1, a2, a3, bB0, bB1);

        s0 += ex2f(fmaf(dA0, F_SCALE, -F_SCALE));
        s0 += ex2f(fmaf(dA1, F_SCALE, -F_SCALE));
        s1 += ex2f(fmaf(dA2, F_SCALE, -F_SCALE));
        s1 += ex2f(fmaf(dA3, F_SCALE, -F_SCALE));
        s0 += ex2f(fmaf(dB0, F_SCALE, -F_SCALE));
        s0 += ex2f(fmaf(dB1, F_SCALE, -F_SCALE));
        s1 += ex2f(fmaf(dB2, F_SCALE, -F_SCALE));
        s1 += ex2f(fmaf(dB3, F_SCALE, -F_SCALE));
    }

    // reduce across the 4 lanes of each row-quad (cols partition)
    s0 += __shfl_xor_sync(0xFFFFFFFFu, s0, 1);
    s0 += __shfl_xor_sync(0xFFFFFFFFu, s0, 2);
    s1 += __shfl_xor_sync(0xFFFFFFFFu, s1, 1);
    s1 += __shfl_xor_sync(0xFFFFFFFFu, s1, 2);

    float loss = 0.f;
    if (t == 0) {
#pragma unroll
        for (int rr = 0; rr < 2; rr++) {
            int r = (rr == 0) ? r0 : r0 + 8;
            float sum = (rr == 0) ? s0 : s1;
            size_t grow = (size_t)b * Sn + r;
            const float4* qr = reinterpret_cast<const float4*>(g_fq + grow * OUTC);
            const float4* kr = reinterpret_cast<const float4*>(g_fk + grow * OUTC);
            float d = 0.f;
#pragma unroll
            for (int jj = 0; jj < 4; jj++) {
                float4 qv = __ldg(&qr[jj]);
                float4 kv = __ldg(&kr[jj]);
                d = fmaf(qv.x, kv.x, d); d = fmaf(qv.y, kv.y, d);
                d = fmaf(qv.z, kv.z, d); d = fmaf(qv.w, kv.w, d);
            }
            loss += F_LN2 * (lg2f(sum) - F_SCALE * (d - 1.0f));
        }
    }

    // warp reduce (non-t0 lanes contribute 0)
#pragma unroll
    for (int o = 16; o > 0; o >>= 1)
        loss += __shfl_xor_sync(0xFFFFFFFFu, loss, o);
    if (lane == 0) s_wred[w] = loss;
    __syncthreads();
    if (tid == 0) {
        float acc = 0.f;
#pragma unroll
        for (int i = 0; i < 8; i++) acc += s_wred[i];
        atomicAdd(out, acc * (1.0f / (float)(Bn * Sn)));
    }
}

// ---------------------------------------------------------------------------
extern "C" void kernel_launch(void* const* d_in, const int* in_sizes, int n_in,
                              void* d_out, int out_size) {
    const float* f_q  = (const float*)d_in[0];
    const float* f_k  = (const float*)d_in[1];
    const float* W0   = (const float*)d_in[2];
    const float* b0   = (const float*)d_in[3];
    const float* W1   = (const float*)d_in[4];
    const float* b1   = (const float*)d_in[5];
    const int*   c_id = (const int*)d_in[6];
    const int*   n_id = (const int*)d_in[7];
    float* out = (float*)d_out;

    int mlp_smem = (256 * XPAD + 64 * 64 + 64 * 16 + 64 + 16) * (int)sizeof(float);
    cudaFuncSetAttribute(mlp_kernel,
                         cudaFuncAttributeMaxDynamicSharedMemorySize, mlp_smem);
    int gram_smem = Sn * 8 * (int)sizeof(uint32_t);   // 64 KB
    cudaFuncSetAttribute(gram_kernel,
                         cudaFuncAttributeMaxDynamicSharedMemorySize, gram_smem);

    gather_diff_kernel<<<2 * Bn * Cn, 256>>>(f_q, f_k, c_id, n_id, out);
    mlp_kernel<<<16 * 8, 256, mlp_smem>>>(W0, b0, W1, b1);
    gram_kernel<<<Bn * 16, 256, gram_smem>>>(out);
}